// round 3
// baseline (speedup 1.0000x reference)
#include <cuda_runtime.h>
#include <cstdint>

#define EPSF 1e-8f
#define PIF  3.14159265358979323846f

constexpr int PLANE   = 512 * 512;   // 262144
constexpr int NB      = 16;          // batches
constexpr int NBC     = NB * 3;      // 48 (batch,channel) planes
constexpr int CHUNKS  = 32;          // reduction chunks per plane
constexpr int P4      = PLANE / 4;   // 65536 float4 per plane

__device__ float g_partials[NBC * CHUNKS];
__device__ float g_hue_bias[NB];

// ---------------------------------------------------------------------------
// Kernel 1: partial sums per (b,c) plane. Deterministic tree reduction.
// grid = NBC * CHUNKS blocks of 256 threads; each block sums 8192 floats.
// ---------------------------------------------------------------------------
__global__ void reduce_kernel(const float* __restrict__ img) {
    __shared__ float sdata[256];
    int bc    = blockIdx.x / CHUNKS;
    int chunk = blockIdx.x % CHUNKS;
    const float4* p = reinterpret_cast<const float4*>(img) +
                      (size_t)bc * P4 + (size_t)chunk * (P4 / CHUNKS);
    int t = threadIdx.x;
    float s = 0.f;
#pragma unroll
    for (int i = 0; i < 8; ++i) {
        float4 v = p[i * 256 + t];
        s += (v.x + v.y) + (v.z + v.w);
    }
    sdata[t] = s;
    __syncthreads();
#pragma unroll
    for (int off = 128; off > 0; off >>= 1) {
        if (t < off) sdata[t] += sdata[t + off];
        __syncthreads();
    }
    if (t == 0) g_partials[blockIdx.x] = sdata[0];
}

// ---------------------------------------------------------------------------
// Kernel 2: finish means + tiny MLP -> g_hue_bias[b]. 1 block, 64 threads.
// ---------------------------------------------------------------------------
__global__ void mlp_kernel(const float* __restrict__ w1, const float* __restrict__ b1,
                           const float* __restrict__ w2, const float* __restrict__ b2) {
    __shared__ float pooled[NBC];
    int t = threadIdx.x;
    if (t < NBC) {
        float s = 0.f;
#pragma unroll
        for (int i = 0; i < CHUNKS; ++i) s += g_partials[t * CHUNKS + i];
        pooled[t] = s * (1.0f / (float)PLANE);
    }
    __syncthreads();
    if (t < NB) {
        float acc = b2[0];
#pragma unroll
        for (int j = 0; j < 8; ++j) {
            float hj = b1[j];
#pragma unroll
            for (int c = 0; c < 3; ++c) hj += pooled[t * 3 + c] * w1[j * 3 + c];
            hj = fmaxf(hj, 0.f);
            acc += hj * w2[j];
        }
        g_hue_bias[t] = tanhf(acc) * 0.5f;
    }
}

// ---------------------------------------------------------------------------
// Per-pixel transform (faithful to the jnp reference, incl. where-precedence
// and python-mod semantics).
// ---------------------------------------------------------------------------
__device__ __forceinline__ void px(float r, float g, float bb, float noise,
                                   float hb, float dk, float ng, float bg,
                                   float& ro, float& go, float& bo) {
    float value = fmaxf(r, fmaxf(g, bb));
    float mn    = fminf(r, fminf(g, bb));
    float inv_d = __fdividef(1.f, value - mn + EPSF);

    float hue = 0.f;
    if (bb == value) hue = 4.f + (r - g) * inv_d;
    if (g  == value) hue = 2.f + (bb - r) * inv_d;
    if (r  == value) {
        float x = (g - bb) * inv_d;
        float m = fmodf(x, 6.f);
        if (m < 0.f) m += 6.f;          // python-mod sign convention
        hue = m;
    }
    if (mn == value) hue = 0.f;
    hue *= (1.f / 6.f);

    float sat = (value == 0.f) ? 0.f
              : (value - mn) * __fdividef(1.f, value + EPSF);

    // hue4 = mod(hue + hue_bias, 1)
    float hue4 = hue + hb;
    hue4 -= floorf(hue4);

    float k = fminf(fmaxf(dk + ng * noise - bg * value, 0.05f), 2.0f);

    float s_half = __sinf(value * (0.5f * PIF)) + EPSF;
    float cs = __powf(s_half, k);        // == cs2 (v = clip(value,0,1) = value)

    float sn, cn;
    __sincosf((2.0f * PIF) * hue4, &sn, &cn);
    float Hc = cs * sat * cn;
    float Vc = cs * sat * sn;

    float Hp = fminf(fmaxf(Hc, -1.f), 1.f);
    float Vp = fminf(fmaxf(Vc, -1.f), 1.f);
    float v  = fminf(fmaxf(value, 0.f), 1.f);

    float inv_cs2 = __fdividef(1.f, cs + EPSF);
    Hp = fminf(fmaxf(Hp * inv_cs2, -1.f), 1.f);
    Vp = fminf(fmaxf(Vp * inv_cs2, -1.f), 1.f);

    float h = atan2f(Vp + EPSF, Hp + EPSF) * (1.0f / (2.0f * PIF));
    h -= floorf(h);          // mod(.,1)
    h = h - hb;
    h -= floorf(h);          // mod(.,1)

    float s = fminf(fmaxf(__fsqrt_rn(Hp * Hp + Vp * Vp + EPSF), 0.f), 1.f);

    float h6 = h * 6.f;
    float hi = floorf(h6);
    float f  = h6 - hi;
    float p  = v * (1.f - s);
    float q  = v * (1.f - f * s);
    float tt = v * (1.f - (1.f - f) * s);

    int ih = (int)hi;
    switch (ih) {
        case 0: ro = v;  go = tt; bo = p;  break;
        case 1: ro = q;  go = v;  bo = p;  break;
        case 2: ro = p;  go = v;  bo = tt; break;
        case 3: ro = p;  go = q;  bo = v;  break;
        case 4: ro = tt; go = p;  bo = v;  break;
        case 5: ro = v;  go = p;  bo = q;  break;
        default: ro = 0.f; go = 0.f; bo = 0.f; break;
    }
}

// ---------------------------------------------------------------------------
// Kernel 3: main elementwise pass. float4 vectorized, 4 px / thread.
// ---------------------------------------------------------------------------
__global__ void __launch_bounds__(256) hvi_kernel(
    const float* __restrict__ img, const float* __restrict__ noise,
    const float* __restrict__ dk_p, const float* __restrict__ ng_p,
    const float* __restrict__ bg_p, float* __restrict__ out)
{
    int i4 = blockIdx.x * blockDim.x + threadIdx.x;   // [0, NB*P4)
    int batch = i4 >> 16;                             // / P4
    int local = i4 & (P4 - 1);

    const float4* img4 = reinterpret_cast<const float4*>(img);
    const float4* n4p  = reinterpret_cast<const float4*>(noise);
    float4*       o4   = reinterpret_cast<float4*>(out);

    size_t base = (size_t)batch * (3 * P4) + local;
    float4 r4 = img4[base];
    float4 g4 = img4[base + P4];
    float4 b4 = img4[base + 2 * P4];
    float4 n4 = n4p[(size_t)batch * P4 + local];

    float hb = g_hue_bias[batch];
    float dk = dk_p[0], ng = ng_p[0], bg = bg_p[0];

    float4 ro, go, bo;
    px(r4.x, g4.x, b4.x, n4.x, hb, dk, ng, bg, ro.x, go.x, bo.x);
    px(r4.y, g4.y, b4.y, n4.y, hb, dk, ng, bg, ro.y, go.y, bo.y);
    px(r4.z, g4.z, b4.z, n4.z, hb, dk, ng, bg, ro.z, go.z, bo.z);
    px(r4.w, g4.w, b4.w, n4.w, hb, dk, ng, bg, ro.w, go.w, bo.w);

    o4[base]          = ro;
    o4[base + P4]     = go;
    o4[base + 2 * P4] = bo;
}

// ---------------------------------------------------------------------------
// Launch: inputs in metadata order:
// img, noise_map, density_k, noise_gain, bright_gain, w1, b1, w2, b2
// ---------------------------------------------------------------------------
extern "C" void kernel_launch(void* const* d_in, const int* in_sizes, int n_in,
                              void* d_out, int out_size) {
    const float* img   = (const float*)d_in[0];
    const float* noise = (const float*)d_in[1];
    const float* dk    = (const float*)d_in[2];
    const float* ng    = (const float*)d_in[3];
    const float* bg    = (const float*)d_in[4];
    const float* w1    = (const float*)d_in[5];
    const float* b1    = (const float*)d_in[6];
    const float* w2    = (const float*)d_in[7];
    const float* b2    = (const float*)d_in[8];
    float* out = (float*)d_out;

    reduce_kernel<<<NBC * CHUNKS, 256>>>(img);
    mlp_kernel<<<1, 64>>>(w1, b1, w2, b2);
    hvi_kernel<<<(NB * P4) / 256, 256>>>(img, noise, dk, ng, bg, out);
}